// round 13
// baseline (speedup 1.0000x reference)
#include <cuda_runtime.h>
#include <cuda_fp16.h>
#include <cstdint>

// Problem shapes (fixed)
#define B_  8
#define C_  64
#define N_  2000
#define T_  12
#define E_  64000
#define HID_ 32

// Scratch
__device__ float g_M1[C_ * C_];            // M1[cin*64 + cout]
__device__ float g_M2[C_ * C_];
__device__ float g_lt[B_ * C_ * N_];       // [b][c][n]
__device__ float g_rt[B_ * C_ * N_];
// fp16 tables, flat layout [b][n][64c]; uint2 units: row stride 16.
__device__ __half g_Ah[B_ * N_ * C_];      // includes conv_b
__device__ __half g_Bh[B_ * N_ * C_];

__device__ __forceinline__ unsigned pack_half2(float a, float b) {
    __half2 h = __floats2half2_rn(a, b);
    return *reinterpret_cast<unsigned*>(&h);
}

// ---------------------------------------------------------------------------
// Kernel 1: fold. M1[cin][cout] = s1*sum_h W3[cin,h]*cw[cout,h];
//                 M2[cin][cout] = s2*sum_h W4[cin,h]*cw[cout,32+h].
// ---------------------------------------------------------------------------
__global__ __launch_bounds__(128) void fold_kernel(const float* __restrict__ W3,
                                                   const float* __restrict__ W4,
                                                   const float* __restrict__ cw,
                                                   const float* __restrict__ s1p,
                                                   const float* __restrict__ s2p) {
    const int cin = blockIdx.x;
    const int t = threadIdx.x;
    const int mat = t >> 6;
    const int cout = t & 63;

    const float* wrow = mat ? (W4 + cin * HID_) : (W3 + cin * HID_);
    const float sc = mat ? __ldg(s2p) : __ldg(s1p);
    const float4* cwp = reinterpret_cast<const float4*>(cw + cout * 64 + mat * 32);
    const float4* wp = reinterpret_cast<const float4*>(wrow);

    float acc = 0.f;
#pragma unroll
    for (int q = 0; q < 8; q++) {
        float4 w = __ldg(wp + q);
        float4 c = __ldg(cwp + q);
        acc = fmaf(w.x, c.x, acc);
        acc = fmaf(w.y, c.y, acc);
        acc = fmaf(w.z, c.z, acc);
        acc = fmaf(w.w, c.w, acc);
    }
    (mat ? g_M2 : g_M1)[cin * 64 + cout] = acc * sc;
}

// ---------------------------------------------------------------------------
// Kernel 2: time reduction, smem-staged for fully coalesced global reads.
// Block handles one 256-n chunk of one (b,c) row: 768 float4 = 12 KB staged
// coalesced (4 wavefronts per LDG.128), then 48B-stride LDS.128 reads
// (12t%32 bank walk -> conflict-free).
// Grid (8 chunks, 64 c, 8 b) x 256 threads.
// ---------------------------------------------------------------------------
__global__ __launch_bounds__(256) void reduce_kernel(const float* __restrict__ x) {
    __shared__ float4 sx[768];        // 12 KB

    const int t = threadIdx.x;
    const int n0 = blockIdx.x * 256;
    const int c = blockIdx.y;
    const int b = blockIdx.z;

    const size_t rowf4 = (size_t)(b * C_ + c) * (N_ * 3);   // row base in f4
    const int f4base = n0 * 3;                               // within row

#pragma unroll
    for (int k = 0; k < 3; k++) {
        int i = t + 256 * k;
        if (f4base + i < N_ * 3)
            sx[i] = __ldg(reinterpret_cast<const float4*>(x) + rowf4 + f4base + i);
    }
    __syncthreads();

    const int n = n0 + t;
    if (n >= N_) return;

    float4 v0 = sx[3 * t], v1 = sx[3 * t + 1], v2 = sx[3 * t + 2];
    float xv[12] = {v0.x, v0.y, v0.z, v0.w,
                    v1.x, v1.y, v1.z, v1.w,
                    v2.x, v2.y, v2.z, v2.w};
    float lt = 0.f, s = 0.f;
#pragma unroll
    for (int tt = 0; tt < T_; tt++) {
        lt = fmaf(xv[tt], (float)tt * (1.0f / 11.0f), lt);
        s += xv[tt];
    }
    const size_t o = (size_t)(b * C_ + c) * N_ + n;
    g_lt[o] = lt;
    g_rt[o] = s - lt;    // t_dn = 1 - t_up
}

// ---------------------------------------------------------------------------
// Kernel 3: project. A[b,n,:] = lt[b,:,n]@M1 + cb; Bv = rt[b,:,n]@M2. fp16 out.
// Grid (32 n-tiles, 8 b) x 256 threads, 64 KB dynamic smem.
// ---------------------------------------------------------------------------
__global__ __launch_bounds__(256) void project_kernel(const float* __restrict__ conv_b) {
    extern __shared__ float4 sm[];
    float4* sM1  = sm;            // [c][co4]  64*16 = 1024 f4 (16 KB)
    float4* sM2  = sm + 1024;     // 16 KB
    float4* slt4 = sm + 2048;     // [c][n4]   16 KB
    float4* srt4 = sm + 3072;     // 16 KB
    float* sltf = reinterpret_cast<float*>(slt4);
    float* srtf = reinterpret_cast<float*>(srt4);

    const int tid = threadIdx.x;
    const int b = blockIdx.y;
    const int n0 = blockIdx.x * 64;

    {
        const float4* m1g = reinterpret_cast<const float4*>(g_M1);
        const float4* m2g = reinterpret_cast<const float4*>(g_M2);
#pragma unroll
        for (int k = 0; k < 4; k++) {
            int i = tid + 256 * k;
            sM1[i] = m1g[i];
            sM2[i] = m2g[i];
        }
    }

#pragma unroll
    for (int k = 0; k < 16; k++) {
        int i = tid + 256 * k;
        int c = i >> 6;
        int nl = i & 63;
        int n = n0 + nl;
        float lv = 0.f, rv = 0.f;
        if (n < N_) {
            size_t o = (size_t)(b * C_ + c) * N_ + n;
            lv = __ldg(g_lt + o);
            rv = __ldg(g_rt + o);
        }
        sltf[i] = lv;
        srtf[i] = rv;
    }
    __syncthreads();

    const int cg = tid & 15;          // co4 group
    const int ng = tid >> 4;          // n4 group

    float4 a0 = {0,0,0,0}, a1 = {0,0,0,0}, a2 = {0,0,0,0}, a3 = {0,0,0,0};
    float4 b0 = {0,0,0,0}, b1 = {0,0,0,0}, b2 = {0,0,0,0}, b3 = {0,0,0,0};

#pragma unroll 16
    for (int c = 0; c < 64; c++) {
        float4 m1 = sM1[c * 16 + cg];
        float4 m2 = sM2[c * 16 + cg];
        float4 l = slt4[c * 16 + ng];
        float4 r = srt4[c * 16 + ng];

        a0.x = fmaf(l.x, m1.x, a0.x); a0.y = fmaf(l.x, m1.y, a0.y);
        a0.z = fmaf(l.x, m1.z, a0.z); a0.w = fmaf(l.x, m1.w, a0.w);
        a1.x = fmaf(l.y, m1.x, a1.x); a1.y = fmaf(l.y, m1.y, a1.y);
        a1.z = fmaf(l.y, m1.z, a1.z); a1.w = fmaf(l.y, m1.w, a1.w);
        a2.x = fmaf(l.z, m1.x, a2.x); a2.y = fmaf(l.z, m1.y, a2.y);
        a2.z = fmaf(l.z, m1.z, a2.z); a2.w = fmaf(l.z, m1.w, a2.w);
        a3.x = fmaf(l.w, m1.x, a3.x); a3.y = fmaf(l.w, m1.y, a3.y);
        a3.z = fmaf(l.w, m1.z, a3.z); a3.w = fmaf(l.w, m1.w, a3.w);

        b0.x = fmaf(r.x, m2.x, b0.x); b0.y = fmaf(r.x, m2.y, b0.y);
        b0.z = fmaf(r.x, m2.z, b0.z); b0.w = fmaf(r.x, m2.w, b0.w);
        b1.x = fmaf(r.y, m2.x, b1.x); b1.y = fmaf(r.y, m2.y, b1.y);
        b1.z = fmaf(r.y, m2.z, b1.z); b1.w = fmaf(r.y, m2.w, b1.w);
        b2.x = fmaf(r.z, m2.x, b2.x); b2.y = fmaf(r.z, m2.y, b2.y);
        b2.z = fmaf(r.z, m2.z, b2.z); b2.w = fmaf(r.z, m2.w, b2.w);
        b3.x = fmaf(r.w, m2.x, b3.x); b3.y = fmaf(r.w, m2.y, b3.y);
        b3.z = fmaf(r.w, m2.z, b3.z); b3.w = fmaf(r.w, m2.w, b3.w);
    }

    float4 cbv = reinterpret_cast<const float4*>(conv_b)[cg];
    uint2* gA2 = reinterpret_cast<uint2*>(g_Ah);
    uint2* gB2 = reinterpret_cast<uint2*>(g_Bh);

    float4 av[4] = {a0, a1, a2, a3};
    float4 bv[4] = {b0, b1, b2, b3};
#pragma unroll
    for (int i = 0; i < 4; i++) {
        int n = n0 + ng * 4 + i;
        if (n < N_) {
            size_t o = ((size_t)b * N_ + n) * 16 + cg;
            float4 aa = av[i];
            aa.x += cbv.x; aa.y += cbv.y; aa.z += cbv.z; aa.w += cbv.w;
            uint2 ua, ub;
            ua.x = pack_half2(aa.x, aa.y);
            ua.y = pack_half2(aa.z, aa.w);
            ub.x = pack_half2(bv[i].x, bv[i].y);
            ub.y = pack_half2(bv[i].z, bv[i].w);
            gA2[o] = ua;
            gB2[o] = ub;
        }
    }
}

// ---------------------------------------------------------------------------
// Kernel 4: gather, 4-edge ILP. Grid (E/128, 2 chalf, B), 256 threads.
// 8 thr/edge, uint2 loads; 8 independent gathered loads in flight per thread.
// ---------------------------------------------------------------------------
__global__ __launch_bounds__(256) void gather_add_kernel(const int* __restrict__ idx,
                                                         const int* __restrict__ idy,
                                                         float4* __restrict__ out) {
    const int tid = threadIdx.x;
    const int chalf = blockIdx.y;     // 0..1
    const int b = blockIdx.z;         // 0..7
    const int el = tid >> 3;          // 0..31
    const int q = tid & 7;            // uint2 within 64B half-row
    const int cq = chalf * 8 + q;
    const int ebase = blockIdx.x * 128 + el;

    int n1[4], n2[4];
#pragma unroll
    for (int j = 0; j < 4; j++) {
        n1[j] = __ldg(idx + ebase + 32 * j);
        n2[j] = __ldg(idy + ebase + 32 * j);
    }

    const uint2* __restrict__ A2 = reinterpret_cast<const uint2*>(g_Ah);
    const uint2* __restrict__ B2 = reinterpret_cast<const uint2*>(g_Bh);

    uint2 ua[4], ub[4];
#pragma unroll
    for (int j = 0; j < 4; j++) {
        ua[j] = __ldg(A2 + ((size_t)b * N_ + n1[j]) * 16 + cq);
        ub[j] = __ldg(B2 + ((size_t)b * N_ + n2[j]) * 16 + cq);
    }

#pragma unroll
    for (int j = 0; j < 4; j++) {
        float2 a0 = __half22float2(*reinterpret_cast<__half2*>(&ua[j].x));
        float2 a1 = __half22float2(*reinterpret_cast<__half2*>(&ua[j].y));
        float2 v0 = __half22float2(*reinterpret_cast<__half2*>(&ub[j].x));
        float2 v1 = __half22float2(*reinterpret_cast<__half2*>(&ub[j].y));
        out[((size_t)b * E_ + ebase + 32 * j) * 16 + cq] =
            make_float4(a0.x + v0.x, a0.y + v0.y, a1.x + v1.x, a1.y + v1.y);
    }
}

// ---------------------------------------------------------------------------
// Launch. Inputs: x, idx, idy, W1_scale, W2_scale, W3, W4, conv_w, conv_b
// ---------------------------------------------------------------------------
extern "C" void kernel_launch(void* const* d_in, const int* in_sizes, int n_in,
                              void* d_out, int out_size) {
    const float* x   = (const float*)d_in[0];
    const int* idx   = (const int*)d_in[1];
    const int* idy   = (const int*)d_in[2];
    const float* s1  = (const float*)d_in[3];
    const float* s2  = (const float*)d_in[4];
    const float* W3  = (const float*)d_in[5];
    const float* W4  = (const float*)d_in[6];
    const float* cw  = (const float*)d_in[7];
    const float* cb  = (const float*)d_in[8];
    float4* out = (float4*)d_out;

    fold_kernel<<<64, 128>>>(W3, W4, cw, s1, s2);

    dim3 grdR(8, 64, 8);
    reduce_kernel<<<grdR, 256>>>(x);

    const int smem_bytes = 4096 * sizeof(float4);   // 64 KB
    cudaFuncSetAttribute(project_kernel,
                         cudaFuncAttributeMaxDynamicSharedMemorySize, smem_bytes);
    dim3 grdP(32, 8);
    project_kernel<<<grdP, 256, smem_bytes>>>(cb);

    dim3 grdG(E_ / 128, 2, B_);       // (500, 2, 8) = 8000 blocks
    gather_add_kernel<<<grdG, 256>>>(idx, idy, out);
}